// round 14
// baseline (speedup 1.0000x reference)
#include <cuda_runtime.h>
#include <cuda_fp16.h>
#include <cstdint>

#define BATCH 16
#define CDIM 256
#define HWDIM 2304
#define PB (CDIM * HWDIM)

#define NST 3
#define STG2 30720u                 // Ahi+Alo+Bhi, 128 rows x 80B each
#define STG1 20480u                 // Ahi+Bhi
#define SMEM2 (NST * STG2)          // 92160
#define SMEM1 (NST * STG1)          // 61440

#define NPART_PER_B 576             // cast_sumsq CTAs per batch
#define NPART (BATCH * NPART_PER_B) // 9216

#define G1_MB (HWDIM / 128)         // 18 m-blocks for GEMM1
#define G2_MB (CDIM / 128)          // 2  m-blocks for GEMM2

// ---------------------------------------------------------------------------
// Device scratch (allocation-free)
// ---------------------------------------------------------------------------
__device__ float g_inv[BATCH];
__device__ float g_part[NPART];
__device__ float g_T[(size_t)BATCH * PB];
__device__ __align__(1024) __half g_Xhi[(size_t)BATCH * PB];
__device__ __align__(1024) __half g_XThi[(size_t)BATCH * PB];
__device__ __align__(1024) __half g_Whi[CDIM * CDIM];
__device__ __align__(1024) __half g_Wlo[CDIM * CDIM];
__device__ __align__(1024) __half g_Shat[(size_t)BATCH * HWDIM * HWDIM];  // 170MB, scaled S
__device__ __align__(1024) __half g_TThi[(size_t)BATCH * PB];

// ---------------------------------------------------------------------------
// fp16 helpers
// ---------------------------------------------------------------------------
__device__ __forceinline__ uint32_t packhf(float a, float b) {
    __half ha = __float2half_rn(a), hb = __float2half_rn(b);
    return (uint32_t)__half_as_ushort(ha) | ((uint32_t)__half_as_ushort(hb) << 16);
}

// ---------------------------------------------------------------------------
// fused: f32 -> fp16 cast (flat) + per-CTA partial sum of squares
// ---------------------------------------------------------------------------
__global__ void cast_sumsq(const float4* __restrict__ in, uint2* __restrict__ hi) {
    const int i = blockIdx.x * blockDim.x + threadIdx.x;   // exactly BATCH*PB/4 threads
    float4 v = in[i];
    uint2 hp;
    hp.x = packhf(v.x, v.y);
    hp.y = packhf(v.z, v.w);
    hi[i] = hp;
    float s = v.x * v.x + v.y * v.y + v.z * v.z + v.w * v.w;
    __shared__ float red[256];
    red[threadIdx.x] = s;
    __syncthreads();
    for (int off = 128; off > 0; off >>= 1) {
        if (threadIdx.x < (unsigned)off) red[threadIdx.x] += red[threadIdx.x + off];
        __syncthreads();
    }
    if (threadIdx.x == 0) g_part[blockIdx.x] = red[0];
}

// grid: BATCH x 256 threads; reduce 576 partials per batch -> 1/sum
__global__ void finalize_inv() {
    const int b = blockIdx.x;
    float s = 0.f;
    for (int i = threadIdx.x; i < NPART_PER_B; i += 256)
        s += g_part[b * NPART_PER_B + i];
    __shared__ float red[256];
    red[threadIdx.x] = s;
    __syncthreads();
    for (int off = 128; off > 0; off >>= 1) {
        if (threadIdx.x < (unsigned)off) red[threadIdx.x] += red[threadIdx.x + off];
        __syncthreads();
    }
    if (threadIdx.x == 0) g_inv[b] = 1.0f / red[0];
}

// f32 -> fp16 hi/lo split (flat) — W only
__global__ void split_flat(const float4* __restrict__ in,
                           uint2* __restrict__ hi, uint2* __restrict__ lo, int n4) {
    int i = blockIdx.x * blockDim.x + threadIdx.x;
    if (i >= n4) return;
    float4 v = in[i];
    __half h0 = __float2half_rn(v.x), h1 = __float2half_rn(v.y);
    __half h2 = __float2half_rn(v.z), h3 = __float2half_rn(v.w);
    uint2 hp, lp;
    hp.x = (uint32_t)__half_as_ushort(h0) | ((uint32_t)__half_as_ushort(h1) << 16);
    hp.y = (uint32_t)__half_as_ushort(h2) | ((uint32_t)__half_as_ushort(h3) << 16);
    lp.x = packhf(v.x - __half2float(h0), v.y - __half2float(h1));
    lp.y = packhf(v.z - __half2float(h2), v.w - __half2float(h3));
    hi[i] = hp;
    lo[i] = lp;
}

// per-batch transpose + fp16 cast (hi only), PACKED uint32 stores:
// in [rows,cols] f32 -> out [cols,rows] fp16; 256 threads, 32x32 tiles
__global__ void transpose_cast(const float* __restrict__ in,
                               __half* __restrict__ hi, int rows, int cols) {
    __shared__ float t[32][33];
    const size_t off = (size_t)blockIdx.z * rows * cols;
    const int c0 = blockIdx.x * 32, r0 = blockIdx.y * 32;
    const int x = threadIdx.x & 31, y0 = threadIdx.x >> 5;
#pragma unroll
    for (int yy = y0; yy < 32; yy += 8)
        t[yy][x] = in[off + (size_t)(r0 + yy) * cols + c0 + x];
    __syncthreads();
    // store phase: sx handles output rows r0+2sx, r0+2sx+1 packed as uint32
    const int sx = threadIdx.x & 15, sy = threadIdx.x >> 4;
#pragma unroll
    for (int cc = sy; cc < 32; cc += 16) {
        uint32_t pk = packhf(t[2 * sx][cc], t[2 * sx + 1][cc]);
        *(uint32_t*)(hi + off + (size_t)(c0 + cc) * rows + r0 + 2 * sx) = pk;
    }
}

// ---------------------------------------------------------------------------
// PTX helpers (sm_80 baseline — compiles on plain compute_103)
// ---------------------------------------------------------------------------
__device__ __forceinline__ uint32_t s2u(const void* p) {
    uint32_t a;
    asm("{ .reg .u64 t; cvta.to.shared.u64 t, %1; cvt.u32.u64 %0, t; }" : "=r"(a) : "l"(p));
    return a;
}
__device__ __forceinline__ void cp16(uint32_t d, const void* g) {
    asm volatile("cp.async.cg.shared.global [%0], [%1], 16;" :: "r"(d), "l"(g));
}
#define LDM4(r, addr) \
    asm volatile("ldmatrix.sync.aligned.m8n8.x4.shared.b16 {%0,%1,%2,%3}, [%4];" \
        : "=r"((r)[0]), "=r"((r)[1]), "=r"((r)[2]), "=r"((r)[3]) : "r"(addr))
#define MMAH(c, a0, a1, a2, a3, b0, b1) \
    asm volatile("mma.sync.aligned.m16n8k16.row.col.f32.f16.f16.f32 " \
        "{%0,%1,%2,%3}, {%4,%5,%6,%7}, {%8,%9}, {%0,%1,%2,%3};" \
        : "+f"((c)[0]), "+f"((c)[1]), "+f"((c)[2]), "+f"((c)[3]) \
        : "r"(a0), "r"(a1), "r"(a2), "r"(a3), "r"(b0), "r"(b1))

// ---------------------------------------------------------------------------
// Combined GEMM1+GEMM2 kernel, CTA 128x128, warp tile 64x32, KC=32.
// grid (18, 20, 16):
//   blockIdx.y <  18 : G1 (1-term)  Shat[m,n] = relu((Xhi @ XThi^T)/256)^2
//   blockIdx.y >= 18 : G2 (2-term)  T[m,n]    = (Whi+Wlo) @ XThi^T + bias[m]
// Shared structure: N=2304, K=256, B = XThi (batch stride PB), lda=ldb=256.
// Stage layout (80B row stride): Ahi@0, Alo@10240 (G2 only), Bhi@20480
// ---------------------------------------------------------------------------
__global__ void __launch_bounds__(256, 2)
mm_g12(const __half* __restrict__ Xhi, const __half* __restrict__ Whi,
       const __half* __restrict__ Wlo, const __half* __restrict__ XThi,
       const float* __restrict__ bias)
{
    extern __shared__ char smv[];
    const uint32_t sb = s2u(smv);
    const int tid = threadIdx.x;
    const int bz = blockIdx.z;
    const bool isG2 = ((int)blockIdx.y >= G1_MB);
    const int m0 = (isG2 ? (int)blockIdx.y - G1_MB : (int)blockIdx.y) * 128;
    const int n0 = blockIdx.x * 128;
    const int w = tid >> 5, l = tid & 31;
    const int wm = w >> 2, wn = w & 3;       // 2 x 4 warps, warp tile 64x32

    // loader: row = tid>>1 (128 rows), 32B chunk = (tid&1)
    const int r = tid >> 1, c = tid & 1;
    const __half* Abase = isG2 ? Whi : (Xhi + (size_t)bz * PB);
    const __half* pAh = Abase + (size_t)(m0 + r) * CDIM + c * 16;
    const __half* pAl = Wlo + (size_t)(m0 + r) * CDIM + c * 16;   // G2 only
    const __half* pBh = XThi + (size_t)bz * PB + (size_t)(n0 + r) * CDIM + c * 16;
    const uint32_t dA = sb + r * 80 + c * 32;
    const uint32_t dB = sb + 20480u + r * 80 + c * 32;

    // fragment lane addressing (verified scheme, 80B stride)
    const int sub = l >> 3;
    const uint32_t aOff = (uint32_t)((wm * 64 + (sub & 1) * 8 + (l & 7)) * 80 + (sub >> 1) * 16);
    const uint32_t bOff = (uint32_t)(20480u + (wn * 32 + (l >> 4) * 8 + (l & 7)) * 80 + ((l >> 3) & 1) * 16);

    float acc[4][4][4];
#pragma unroll
    for (int i = 0; i < 4; i++)
#pragma unroll
        for (int j = 0; j < 4; j++)
#pragma unroll
            for (int q = 0; q < 4; q++) acc[i][j][q] = 0.f;

#define LOAD_STAGE(kc, slot) do { \
        const uint32_t so = (uint32_t)(slot) * STG2; \
        const int ko = (kc) * 32; \
        cp16(dA + so,      pAh + ko); \
        cp16(dA + so + 16, pAh + ko + 8); \
        cp16(dB + so,      pBh + ko); \
        cp16(dB + so + 16, pBh + ko + 8); \
        if (isG2) { \
            cp16(dA + so + 10240, pAl + ko); \
            cp16(dA + so + 10256, pAl + ko + 8); \
        } \
        asm volatile("cp.async.commit_group;"); \
    } while (0)

    const int KN = CDIM / 32;  // 8
    LOAD_STAGE(0, 0);
    LOAD_STAGE(1, 1);

    int slot = 0;
    for (int kc = 0; kc < KN; kc++) {
        asm volatile("cp.async.wait_group 1;");
        __syncthreads();
        if (kc + 2 < KN) LOAD_STAGE(kc + 2, (kc + 2) % NST);
        const uint32_t s0 = sb + slot * STG2;
        slot++; if (slot == NST) slot = 0;
#pragma unroll
        for (int ks = 0; ks < 2; ks++) {
            uint32_t bfh[4][2];
            const uint32_t b0a = s0 + bOff + ks * 32;
#pragma unroll
            for (int p = 0; p < 2; p++) {
                uint32_t t4[4];
                LDM4(t4, b0a + p * (16 * 80));
                bfh[2 * p][0] = t4[0]; bfh[2 * p][1] = t4[1];
                bfh[2 * p + 1][0] = t4[2]; bfh[2 * p + 1][1] = t4[3];
            }
            const uint32_t a0a = s0 + aOff + ks * 32;
#pragma unroll
            for (int i = 0; i < 4; i++) {
                uint32_t ah[4];
                LDM4(ah, a0a + i * 1280);
#pragma unroll
                for (int j = 0; j < 4; j++)
                    MMAH(acc[i][j], ah[0], ah[1], ah[2], ah[3], bfh[j][0], bfh[j][1]);
                if (isG2) {
                    uint32_t al4[4];
                    LDM4(al4, a0a + i * 1280 + 10240);
#pragma unroll
                    for (int j = 0; j < 4; j++)
                        MMAH(acc[i][j], al4[0], al4[1], al4[2], al4[3], bfh[j][0], bfh[j][1]);
                }
            }
        }
    }

    // epilogue
    const int quad = l >> 2, tq = l & 3;
#pragma unroll
    for (int i = 0; i < 4; i++) {
#pragma unroll
        for (int half = 0; half < 2; half++) {
            const int rr = m0 + wm * 64 + i * 16 + quad + half * 8;
            float bvv = 0.f;
            if (isG2) bvv = bias[rr];
#pragma unroll
            for (int j = 0; j < 4; j++) {
                const int col = n0 + wn * 32 + j * 8 + tq * 2;
                float v0 = acc[i][j][half * 2 + 0];
                float v1 = acc[i][j][half * 2 + 1];
                if (!isG2) {
                    // Shat = relu(acc/256)^2  (fp16-range-safe scaled S)
                    v0 = fmaxf(v0 * 0.00390625f, 0.f); v0 *= v0;
                    v1 = fmaxf(v1 * 0.00390625f, 0.f); v1 *= v1;
                    size_t base = (size_t)bz * HWDIM * HWDIM + (size_t)rr * HWDIM + col;
                    *(uint32_t*)(g_Shat + base) = packhf(v0, v1);
                } else {
                    float2 vv; vv.x = v0 + bvv; vv.y = v1 + bvv;
                    *(float2*)(g_T + (size_t)bz * PB + (size_t)rr * HWDIM + col) = vv;
                }
            }
        }
    }
#undef LOAD_STAGE
}

// ---------------------------------------------------------------------------
// GEMM3 kernel (1-term), unchanged from R13: Y = Shat @ TThi^T * inv^2*2^16
// ---------------------------------------------------------------------------
__global__ void __launch_bounds__(256, 2)
mm_g3(const __half* __restrict__ Ah, const __half* __restrict__ Bh,
      float* __restrict__ outY)
{
    extern __shared__ char smv[];
    const uint32_t sb = s2u(smv);
    const int tid = threadIdx.x;
    const int bz = blockIdx.z;
    const int m0 = blockIdx.y * 128, n0 = blockIdx.x * 128;
    const int w = tid >> 5, l = tid & 31;
    const int wm = w >> 2, wn = w & 3;

    const int r = tid >> 1, c = tid & 1;
    const __half* pAh = Ah + (size_t)bz * HWDIM * HWDIM + (size_t)(m0 + r) * HWDIM + c * 16;
    const __half* pBh = Bh + (size_t)bz * PB + (size_t)(n0 + r) * HWDIM + c * 16;
    const uint32_t dA = sb + r * 80 + c * 32;
    const uint32_t dB = sb + 10240u + r * 80 + c * 32;

    const int sub = l >> 3;
    const uint32_t aOff = (uint32_t)((wm * 64 + (sub & 1) * 8 + (l & 7)) * 80 + (sub >> 1) * 16);
    const uint32_t bOff = (uint32_t)(10240u + (wn * 32 + (l >> 4) * 8 + (l & 7)) * 80 + ((l >> 3) & 1) * 16);

    float acc[4][4][4];
#pragma unroll
    for (int i = 0; i < 4; i++)
#pragma unroll
        for (int j = 0; j < 4; j++)
#pragma unroll
            for (int q = 0; q < 4; q++) acc[i][j][q] = 0.f;

#define LOAD_STAGE3(kc, slot) do { \
        const uint32_t so = (uint32_t)(slot) * STG1; \
        const int ko = (kc) * 32; \
        cp16(dA + so,      pAh + ko); \
        cp16(dA + so + 16, pAh + ko + 8); \
        cp16(dB + so,      pBh + ko); \
        cp16(dB + so + 16, pBh + ko + 8); \
        asm volatile("cp.async.commit_group;"); \
    } while (0)

    const int KN = HWDIM / 32;  // 72
    LOAD_STAGE3(0, 0);
    LOAD_STAGE3(1, 1);

    int slot = 0;
    for (int kc = 0; kc < KN; kc++) {
        asm volatile("cp.async.wait_group 1;");
        __syncthreads();
        if (kc + 2 < KN) LOAD_STAGE3(kc + 2, (kc + 2) % NST);
        const uint32_t s0 = sb + slot * STG1;
        slot++; if (slot == NST) slot = 0;
#pragma unroll
        for (int ks = 0; ks < 2; ks++) {
            uint32_t bfh[4][2];
            const uint32_t b0a = s0 + bOff + ks * 32;
#pragma unroll
            for (int p = 0; p < 2; p++) {
                uint32_t t4[4];
                LDM4(t4, b0a + p * (16 * 80));
                bfh[2 * p][0] = t4[0]; bfh[2 * p][1] = t4[1];
                bfh[2 * p + 1][0] = t4[2]; bfh[2 * p + 1][1] = t4[3];
            }
            const uint32_t a0a = s0 + aOff + ks * 32;
#pragma unroll
            for (int i = 0; i < 4; i++) {
                uint32_t ah[4];
                LDM4(ah, a0a + i * 1280);
#pragma unroll
                for (int j = 0; j < 4; j++)
                    MMAH(acc[i][j], ah[0], ah[1], ah[2], ah[3], bfh[j][0], bfh[j][1]);
            }
        }
    }

    const float inv = g_inv[bz];
    const float factor = inv * inv * 65536.f;
    const int quad = l >> 2, tq = l & 3;
#pragma unroll
    for (int i = 0; i < 4; i++) {
#pragma unroll
        for (int half = 0; half < 2; half++) {
            const int rr = m0 + wm * 64 + i * 16 + quad + half * 8;
#pragma unroll
            for (int j = 0; j < 4; j++) {
                const int col = n0 + wn * 32 + j * 8 + tq * 2;
                float2 vv;
                vv.x = acc[i][j][half * 2 + 0] * factor;
                vv.y = acc[i][j][half * 2 + 1] * factor;
                *(float2*)(outY + (size_t)bz * PB + (size_t)rr * CDIM + col) = vv;
            }
        }
    }
#undef LOAD_STAGE3
}

// ---------------------------------------------------------------------------
// Host launch
// ---------------------------------------------------------------------------
extern "C" void kernel_launch(void* const* d_in, const int* in_sizes, int n_in,
                              void* d_out, int out_size)
{
    const float* x    = (const float*)d_in[0];
    const float* W    = (const float*)d_in[1];
    const float* bias = (const float*)d_in[2];
    float* out        = (float*)d_out;

    void *pXhi, *pXThi, *pWhi, *pWlo, *pShat, *pTThi, *pT;
    cudaGetSymbolAddress(&pXhi,  g_Xhi);
    cudaGetSymbolAddress(&pXThi, g_XThi);
    cudaGetSymbolAddress(&pWhi,  g_Whi);
    cudaGetSymbolAddress(&pWlo,  g_Wlo);
    cudaGetSymbolAddress(&pShat, g_Shat);
    cudaGetSymbolAddress(&pTThi, g_TThi);
    cudaGetSymbolAddress(&pT,    g_T);

    static bool attr_done = false;
    if (!attr_done) {
        cudaFuncSetAttribute(mm_g12, cudaFuncAttributeMaxDynamicSharedMemorySize, SMEM2);
        cudaFuncSetAttribute(mm_g3,  cudaFuncAttributeMaxDynamicSharedMemorySize, SMEM1);
        attr_done = true;
    }

    // 1) fused x cast + per-CTA sumsq partials
    cast_sumsq<<<NPART, 256>>>((const float4*)x, (uint2*)pXhi);

    // 2) W split + XT transpose (packed stores)
    split_flat<<<(CDIM * CDIM / 4 + 255) / 256, 256>>>((const float4*)W, (uint2*)pWhi, (uint2*)pWlo, CDIM * CDIM / 4);
    {   // XT = transpose(x viewed [256,2304]) -> [2304,256] fp16
        dim3 g(HWDIM / 32, CDIM / 32, BATCH);
        transpose_cast<<<g, 256>>>(x, (__half*)pXThi, CDIM, HWDIM);
    }

    // 3) Combined GEMM1 (1-term -> Shat) + GEMM2 (2-term -> T)
    mm_g12<<<dim3(HWDIM / 128, G1_MB + G2_MB, BATCH), 256, SMEM2>>>(
        (const __half*)pXhi, (const __half*)pWhi, (const __half*)pWlo,
        (const __half*)pXThi, bias);

    // 4) finalize 1/||x||^2 (only needed by GEMM3)
    finalize_inv<<<BATCH, 256>>>();

    // 5) TT = transpose(T viewed [2304,256]) -> [256,2304] fp16 (packed stores)
    {
        dim3 g(CDIM / 32, HWDIM / 32, BATCH);
        transpose_cast<<<g, 256>>>((const float*)pT, (__half*)pTThi, HWDIM, CDIM);
    }

    // 6) GEMM3 (1-term): Y = Shat @ TThi^T * inv^2*2^16 -> out
    mm_g3<<<dim3(CDIM / 128, HWDIM / 128, BATCH), 256, SMEM1>>>(
        (const __half*)pShat, (const __half*)pTThi, out);
}

// round 15
// speedup vs baseline: 1.0907x; 1.0907x over previous
#include <cuda_runtime.h>
#include <cuda_fp16.h>
#include <cstdint>

#define BATCH 16
#define CDIM 256
#define HWDIM 2304
#define PB (CDIM * HWDIM)

#define STG2 30720u                 // Ahi+Alo+Bhi, 128 rows x 80B each
#define STG1 20480u                 // Ahi+Bhi
#define SMEM_G2 (3 * STG2)          // 92160 (3-stage)
#define SMEM_G1 (4 * STG1)          // 81920 (4-stage)

#define NPART_PER_B 576             // cast_sumsq CTAs per batch
#define NPART (BATCH * NPART_PER_B) // 9216

// ---------------------------------------------------------------------------
// Device scratch (allocation-free)
// ---------------------------------------------------------------------------
__device__ float g_inv[BATCH];
__device__ float g_part[NPART];
__device__ __align__(1024) __half g_Xhi[(size_t)BATCH * PB];
__device__ __align__(1024) __half g_XThi[(size_t)BATCH * PB];
__device__ __align__(1024) __half g_Whi[CDIM * CDIM];
__device__ __align__(1024) __half g_Wlo[CDIM * CDIM];
__device__ __align__(1024) __half g_Shat[(size_t)BATCH * HWDIM * HWDIM];  // 170MB, scaled S
__device__ __align__(1024) __half g_Tf16[(size_t)BATCH * PB];             // fp16 T (flat [256,2304])
__device__ __align__(1024) __half g_TThi[(size_t)BATCH * PB];

// ---------------------------------------------------------------------------
// fp16 helpers
// ---------------------------------------------------------------------------
__device__ __forceinline__ uint32_t packhf(float a, float b) {
    __half ha = __float2half_rn(a), hb = __float2half_rn(b);
    return (uint32_t)__half_as_ushort(ha) | ((uint32_t)__half_as_ushort(hb) << 16);
}

// ---------------------------------------------------------------------------
// fused: f32 -> fp16 cast (flat) + per-CTA partial sum of squares
// ---------------------------------------------------------------------------
__global__ void cast_sumsq(const float4* __restrict__ in, uint2* __restrict__ hi) {
    const int i = blockIdx.x * blockDim.x + threadIdx.x;   // exactly BATCH*PB/4 threads
    float4 v = in[i];
    uint2 hp;
    hp.x = packhf(v.x, v.y);
    hp.y = packhf(v.z, v.w);
    hi[i] = hp;
    float s = v.x * v.x + v.y * v.y + v.z * v.z + v.w * v.w;
    __shared__ float red[256];
    red[threadIdx.x] = s;
    __syncthreads();
    for (int off = 128; off > 0; off >>= 1) {
        if (threadIdx.x < (unsigned)off) red[threadIdx.x] += red[threadIdx.x + off];
        __syncthreads();
    }
    if (threadIdx.x == 0) g_part[blockIdx.x] = red[0];
}

// grid: BATCH x 256 threads; reduce 576 partials per batch -> 1/sum
__global__ void finalize_inv() {
    const int b = blockIdx.x;
    float s = 0.f;
    for (int i = threadIdx.x; i < NPART_PER_B; i += 256)
        s += g_part[b * NPART_PER_B + i];
    __shared__ float red[256];
    red[threadIdx.x] = s;
    __syncthreads();
    for (int off = 128; off > 0; off >>= 1) {
        if (threadIdx.x < (unsigned)off) red[threadIdx.x] += red[threadIdx.x + off];
        __syncthreads();
    }
    if (threadIdx.x == 0) g_inv[b] = 1.0f / red[0];
}

// f32 -> fp16 hi/lo split (flat) — W only
__global__ void split_flat(const float4* __restrict__ in,
                           uint2* __restrict__ hi, uint2* __restrict__ lo, int n4) {
    int i = blockIdx.x * blockDim.x + threadIdx.x;
    if (i >= n4) return;
    float4 v = in[i];
    __half h0 = __float2half_rn(v.x), h1 = __float2half_rn(v.y);
    __half h2 = __float2half_rn(v.z), h3 = __float2half_rn(v.w);
    uint2 hp, lp;
    hp.x = (uint32_t)__half_as_ushort(h0) | ((uint32_t)__half_as_ushort(h1) << 16);
    hp.y = (uint32_t)__half_as_ushort(h2) | ((uint32_t)__half_as_ushort(h3) << 16);
    lp.x = packhf(v.x - __half2float(h0), v.y - __half2float(h1));
    lp.y = packhf(v.z - __half2float(h2), v.w - __half2float(h3));
    hi[i] = hp;
    lo[i] = lp;
}

// per-batch transpose + fp16 cast (f32 input), PACKED uint32 stores
// in [rows,cols] f32 -> out [cols,rows] fp16; 256 threads, 32x32 tiles
__global__ void transpose_cast(const float* __restrict__ in,
                               __half* __restrict__ hi, int rows, int cols) {
    __shared__ float t[32][33];
    const size_t off = (size_t)blockIdx.z * rows * cols;
    const int c0 = blockIdx.x * 32, r0 = blockIdx.y * 32;
    const int x = threadIdx.x & 31, y0 = threadIdx.x >> 5;
#pragma unroll
    for (int yy = y0; yy < 32; yy += 8)
        t[yy][x] = in[off + (size_t)(r0 + yy) * cols + c0 + x];
    __syncthreads();
    const int sx = threadIdx.x & 15, sy = threadIdx.x >> 4;
#pragma unroll
    for (int cc = sy; cc < 32; cc += 16) {
        uint32_t pk = packhf(t[2 * sx][cc], t[2 * sx + 1][cc]);
        *(uint32_t*)(hi + off + (size_t)(c0 + cc) * rows + r0 + 2 * sx) = pk;
    }
}

// same, fp16 input (for TT = transpose of fp16 T view)
__global__ void transpose_h(const __half* __restrict__ in,
                            __half* __restrict__ hi, int rows, int cols) {
    __shared__ float t[32][33];
    const size_t off = (size_t)blockIdx.z * rows * cols;
    const int c0 = blockIdx.x * 32, r0 = blockIdx.y * 32;
    const int x = threadIdx.x & 31, y0 = threadIdx.x >> 5;
#pragma unroll
    for (int yy = y0; yy < 32; yy += 8)
        t[yy][x] = __half2float(in[off + (size_t)(r0 + yy) * cols + c0 + x]);
    __syncthreads();
    const int sx = threadIdx.x & 15, sy = threadIdx.x >> 4;
#pragma unroll
    for (int cc = sy; cc < 32; cc += 16) {
        uint32_t pk = packhf(t[2 * sx][cc], t[2 * sx + 1][cc]);
        *(uint32_t*)(hi + off + (size_t)(c0 + cc) * rows + r0 + 2 * sx) = pk;
    }
}

// ---------------------------------------------------------------------------
// PTX helpers (sm_80 baseline — compiles on plain compute_103)
// ---------------------------------------------------------------------------
__device__ __forceinline__ uint32_t s2u(const void* p) {
    uint32_t a;
    asm("{ .reg .u64 t; cvta.to.shared.u64 t, %1; cvt.u32.u64 %0, t; }" : "=r"(a) : "l"(p));
    return a;
}
__device__ __forceinline__ void cp16(uint32_t d, const void* g) {
    asm volatile("cp.async.cg.shared.global [%0], [%1], 16;" :: "r"(d), "l"(g));
}
#define LDM4(r, addr) \
    asm volatile("ldmatrix.sync.aligned.m8n8.x4.shared.b16 {%0,%1,%2,%3}, [%4];" \
        : "=r"((r)[0]), "=r"((r)[1]), "=r"((r)[2]), "=r"((r)[3]) : "r"(addr))
#define MMAH(c, a0, a1, a2, a3, b0, b1) \
    asm volatile("mma.sync.aligned.m16n8k16.row.col.f32.f16.f16.f32 " \
        "{%0,%1,%2,%3}, {%4,%5,%6,%7}, {%8,%9}, {%0,%1,%2,%3};" \
        : "+f"((c)[0]), "+f"((c)[1]), "+f"((c)[2]), "+f"((c)[3]) \
        : "r"(a0), "r"(a1), "r"(a2), "r"(a3), "r"(b0), "r"(b1))

// ---------------------------------------------------------------------------
// fp16 mma.sync GEMM, CTA 128x128, warp tile 64x32, KC=32, NSTG-stage cp.async
//   D[m,n] = sum_k A[m,k]*B[n,k]   (K-major fp16)
// TERMS=2: ahi*bhi + alo*bhi  (= A*Bhi, A exact)       [G2: 3-stage]
// TERMS=1: ahi*bhi                                      [G1/G3: 4-stage]
// EPI 0: Shat = relu(acc/256)^2 -> g_Shat (fp16)
// EPI 1: T = acc + bias[row]     -> g_Tf16 (fp16, ld 2304)
// EPI 2: Y = acc * inv^2*65536   -> outY (f32, ld 256)
// ---------------------------------------------------------------------------
template <int EPI, int TERMS, int NSTG>
__global__ void __launch_bounds__(256, 2)
mm_fp16(const __half* __restrict__ Ah, const __half* __restrict__ Al,
        const __half* __restrict__ Bh,
        int lda, int ldb, size_t bA, size_t bB, int K,
        const float* __restrict__ bias, float* __restrict__ outY)
{
    constexpr uint32_t STG = (TERMS == 2) ? STG2 : STG1;
    constexpr uint32_t oBh = (TERMS == 2) ? 20480u : 10240u;

    extern __shared__ char smv[];
    const uint32_t sb = s2u(smv);
    const int tid = threadIdx.x;
    const int bz = blockIdx.z;
    const int m0 = blockIdx.y * 128, n0 = blockIdx.x * 128;
    const int w = tid >> 5, l = tid & 31;
    const int wm = w >> 2, wn = w & 3;       // 2 x 4 warps, warp tile 64x32

    // loader: row = tid>>1 (128 rows), 32B chunk = (tid&1)
    const int r = tid >> 1, c = tid & 1;
    const __half* pAh = Ah + (size_t)bz * bA + (size_t)(m0 + r) * lda + c * 16;
    const __half* pAl = (TERMS == 2) ? (Al + (size_t)(m0 + r) * lda + c * 16) : nullptr;
    const __half* pBh = Bh + (size_t)bz * bB + (size_t)(n0 + r) * ldb + c * 16;
    const uint32_t dA = sb + r * 80 + c * 32;
    const uint32_t dB = sb + oBh + r * 80 + c * 32;

    // fragment lane addressing (verified scheme, 80B stride)
    const int sub = l >> 3;
    const uint32_t aOff = (uint32_t)((wm * 64 + (sub & 1) * 8 + (l & 7)) * 80 + (sub >> 1) * 16);
    const uint32_t bOff = (uint32_t)(oBh + (wn * 32 + (l >> 4) * 8 + (l & 7)) * 80 + ((l >> 3) & 1) * 16);

    float acc[4][4][4];
#pragma unroll
    for (int i = 0; i < 4; i++)
#pragma unroll
        for (int j = 0; j < 4; j++)
#pragma unroll
            for (int q = 0; q < 4; q++) acc[i][j][q] = 0.f;

#define LOAD_STAGE(kc, slot) do { \
        const uint32_t so = (uint32_t)(slot) * STG; \
        const int ko = (kc) * 32; \
        cp16(dA + so,      pAh + ko); \
        cp16(dA + so + 16, pAh + ko + 8); \
        cp16(dB + so,      pBh + ko); \
        cp16(dB + so + 16, pBh + ko + 8); \
        if (TERMS == 2) { \
            cp16(dA + so + 10240, pAl + ko); \
            cp16(dA + so + 10256, pAl + ko + 8); \
        } \
        asm volatile("cp.async.commit_group;"); \
    } while (0)

    const int KN = K / 32;
#pragma unroll
    for (int p = 0; p < NSTG - 1; p++) LOAD_STAGE(p, p);

    int slot = 0;
    for (int kc = 0; kc < KN; kc++) {
        if (NSTG == 4) asm volatile("cp.async.wait_group 2;");
        else           asm volatile("cp.async.wait_group 1;");
        __syncthreads();
        if (kc + NSTG - 1 < KN) LOAD_STAGE(kc + NSTG - 1, (kc + NSTG - 1) % NSTG);
        const uint32_t s0 = sb + slot * STG;
        slot++; if (slot == NSTG) slot = 0;
#pragma unroll
        for (int ks = 0; ks < 2; ks++) {
            uint32_t bfh[4][2];
            const uint32_t b0a = s0 + bOff + ks * 32;
#pragma unroll
            for (int p = 0; p < 2; p++) {
                uint32_t t4[4];
                LDM4(t4, b0a + p * (16 * 80));
                bfh[2 * p][0] = t4[0]; bfh[2 * p][1] = t4[1];
                bfh[2 * p + 1][0] = t4[2]; bfh[2 * p + 1][1] = t4[3];
            }
            const uint32_t a0a = s0 + aOff + ks * 32;
#pragma unroll
            for (int i = 0; i < 4; i++) {
                uint32_t ah[4];
                LDM4(ah, a0a + i * 1280);
#pragma unroll
                for (int j = 0; j < 4; j++)
                    MMAH(acc[i][j], ah[0], ah[1], ah[2], ah[3], bfh[j][0], bfh[j][1]);
                if (TERMS == 2) {
                    uint32_t al4[4];
                    LDM4(al4, a0a + i * 1280 + 10240);
#pragma unroll
                    for (int j = 0; j < 4; j++)
                        MMAH(acc[i][j], al4[0], al4[1], al4[2], al4[3], bfh[j][0], bfh[j][1]);
                }
            }
        }
    }

    // epilogue
    float factor = 0.f;
    if (EPI == 2) {
        float inv = g_inv[bz];
        factor = inv * inv * 65536.f;
    }
    const int quad = l >> 2, tq = l & 3;
#pragma unroll
    for (int i = 0; i < 4; i++) {
#pragma unroll
        for (int half = 0; half < 2; half++) {
            const int rr = m0 + wm * 64 + i * 16 + quad + half * 8;
            float bvv = 0.f;
            if (EPI == 1) bvv = bias[rr];
#pragma unroll
            for (int j = 0; j < 4; j++) {
                const int col = n0 + wn * 32 + j * 8 + tq * 2;
                float v0 = acc[i][j][half * 2 + 0];
                float v1 = acc[i][j][half * 2 + 1];
                if (EPI == 0) {
                    // Shat = relu(acc/256)^2  (fp16-range-safe scaled S)
                    v0 = fmaxf(v0 * 0.00390625f, 0.f); v0 *= v0;
                    v1 = fmaxf(v1 * 0.00390625f, 0.f); v1 *= v1;
                    size_t base = (size_t)bz * HWDIM * HWDIM + (size_t)rr * HWDIM + col;
                    *(uint32_t*)(g_Shat + base) = packhf(v0, v1);
                } else if (EPI == 1) {
                    size_t base = (size_t)bz * PB + (size_t)rr * HWDIM + col;
                    *(uint32_t*)(g_Tf16 + base) = packhf(v0 + bvv, v1 + bvv);
                } else {
                    float2 vv; vv.x = v0 * factor; vv.y = v1 * factor;
                    *(float2*)(outY + (size_t)bz * PB + (size_t)rr * CDIM + col) = vv;
                }
            }
        }
    }
#undef LOAD_STAGE
}

// ---------------------------------------------------------------------------
// Host launch
// ---------------------------------------------------------------------------
extern "C" void kernel_launch(void* const* d_in, const int* in_sizes, int n_in,
                              void* d_out, int out_size)
{
    const float* x    = (const float*)d_in[0];
    const float* W    = (const float*)d_in[1];
    const float* bias = (const float*)d_in[2];
    float* out        = (float*)d_out;

    void *pXhi, *pXThi, *pWhi, *pWlo, *pShat, *pTThi, *pTf;
    cudaGetSymbolAddress(&pXhi,  g_Xhi);
    cudaGetSymbolAddress(&pXThi, g_XThi);
    cudaGetSymbolAddress(&pWhi,  g_Whi);
    cudaGetSymbolAddress(&pWlo,  g_Wlo);
    cudaGetSymbolAddress(&pShat, g_Shat);
    cudaGetSymbolAddress(&pTThi, g_TThi);
    cudaGetSymbolAddress(&pTf,   g_Tf16);

    static bool attr_done = false;
    if (!attr_done) {
        cudaFuncSetAttribute(mm_fp16<0, 1, 4>, cudaFuncAttributeMaxDynamicSharedMemorySize, SMEM_G1);
        cudaFuncSetAttribute(mm_fp16<1, 2, 3>, cudaFuncAttributeMaxDynamicSharedMemorySize, SMEM_G2);
        cudaFuncSetAttribute(mm_fp16<2, 1, 4>, cudaFuncAttributeMaxDynamicSharedMemorySize, SMEM_G1);
        attr_done = true;
    }

    // 1) fused x cast + per-CTA sumsq partials
    cast_sumsq<<<NPART, 256>>>((const float4*)x, (uint2*)pXhi);

    // 2) W split + XT transpose (packed stores)
    split_flat<<<(CDIM * CDIM / 4 + 255) / 256, 256>>>((const float4*)W, (uint2*)pWhi, (uint2*)pWlo, CDIM * CDIM / 4);
    {   // XT = transpose(x viewed [256,2304]) -> [2304,256] fp16
        dim3 g(HWDIM / 32, CDIM / 32, BATCH);
        transpose_cast<<<g, 256>>>(x, (__half*)pXThi, CDIM, HWDIM);
    }

    // 3) GEMM2 (2-term, W exact, 3-stage): T = W @ x2hi + bias -> g_Tf16 (fp16)
    mm_fp16<1, 2, 3><<<dim3(HWDIM / 128, CDIM / 128, BATCH), 256, SMEM_G2>>>(
        (const __half*)pWhi, (const __half*)pWlo, (const __half*)pXThi,
        CDIM, CDIM, 0, (size_t)PB, CDIM, bias, nullptr);

    // 4) finalize 1/||x||^2 (only gates GEMM3)
    finalize_inv<<<BATCH, 256>>>();

    // 5) TT = transpose(Tf16 viewed [2304,256]) -> [256,2304] fp16
    {
        dim3 g(CDIM / 32, HWDIM / 32, BATCH);
        transpose_h<<<g, 256>>>((const __half*)pTf, (__half*)pTThi, HWDIM, CDIM);
    }

    // 6) GEMM1 (1-term, 4-stage): Shat = relu((x1hi @ x2hi)/256)^2
    mm_fp16<0, 1, 4><<<dim3(HWDIM / 128, HWDIM / 128, BATCH), 256, SMEM_G1>>>(
        (const __half*)pXhi, nullptr, (const __half*)pXThi,
        CDIM, CDIM, (size_t)PB, (size_t)PB, CDIM, nullptr, nullptr);

    // 7) GEMM3 (1-term, 4-stage): Y = Shat @ TThi^T * inv^2*2^16 -> out
    mm_fp16<2, 1, 4><<<dim3(CDIM / 128, HWDIM / 128, BATCH), 256, SMEM_G1>>>(
        (const __half*)pShat, nullptr, (const __half*)pTThi,
        HWDIM, HWDIM, (size_t)HWDIM * HWDIM, (size_t)PB, HWDIM, nullptr, out);
}

// round 16
// speedup vs baseline: 1.1117x; 1.0193x over previous
#include <cuda_runtime.h>
#include <cuda_fp16.h>
#include <cstdint>

#define BATCH 16
#define CDIM 256
#define HWDIM 2304
#define PB (CDIM * HWDIM)

#define STG2 30720u                 // Ahi+Alo+Bhi, 128 rows x 80B each
#define STG1 20480u                 // Ahi+Bhi
#define SMEM_G2 (3 * STG2)          // 92160 (3-stage)
#define SMEM_G1 (4 * STG1)          // 81920 (4-stage)

#define NPART_PER_B 576             // cast_sumsq CTAs per batch
#define NPART (BATCH * NPART_PER_B) // 9216

// ---------------------------------------------------------------------------
// Device scratch (allocation-free)
// ---------------------------------------------------------------------------
__device__ float g_inv[BATCH];
__device__ float g_part[NPART];
__device__ __align__(1024) __half g_Xhi[(size_t)BATCH * PB];
__device__ __align__(1024) __half g_XThi[(size_t)BATCH * PB];
__device__ __align__(1024) __half g_Whi[CDIM * CDIM];
__device__ __align__(1024) __half g_Wlo[CDIM * CDIM];
__device__ __align__(1024) __half g_Shat[(size_t)BATCH * HWDIM * HWDIM];  // 170MB, scaled S
__device__ __align__(1024) __half g_Tf16[(size_t)BATCH * PB];             // fp16 T (flat [256,2304])
__device__ __align__(1024) __half g_TThi[(size_t)BATCH * PB];

// ---------------------------------------------------------------------------
// fp16 helpers
// ---------------------------------------------------------------------------
__device__ __forceinline__ uint32_t packhf(float a, float b) {
    __half ha = __float2half_rn(a), hb = __float2half_rn(b);
    return (uint32_t)__half_as_ushort(ha) | ((uint32_t)__half_as_ushort(hb) << 16);
}

// ---------------------------------------------------------------------------
// fused: f32 -> fp16 cast (flat) + per-CTA partial sum of squares
// ---------------------------------------------------------------------------
__global__ void cast_sumsq(const float4* __restrict__ in, uint2* __restrict__ hi) {
    const int i = blockIdx.x * blockDim.x + threadIdx.x;   // exactly BATCH*PB/4 threads
    float4 v = in[i];
    uint2 hp;
    hp.x = packhf(v.x, v.y);
    hp.y = packhf(v.z, v.w);
    hi[i] = hp;
    float s = v.x * v.x + v.y * v.y + v.z * v.z + v.w * v.w;
    __shared__ float red[256];
    red[threadIdx.x] = s;
    __syncthreads();
    for (int off = 128; off > 0; off >>= 1) {
        if (threadIdx.x < (unsigned)off) red[threadIdx.x] += red[threadIdx.x + off];
        __syncthreads();
    }
    if (threadIdx.x == 0) g_part[blockIdx.x] = red[0];
}

// grid: BATCH x 256 threads; reduce 576 partials per batch -> 1/sum
__global__ void finalize_inv() {
    const int b = blockIdx.x;
    float s = 0.f;
    for (int i = threadIdx.x; i < NPART_PER_B; i += 256)
        s += g_part[b * NPART_PER_B + i];
    __shared__ float red[256];
    red[threadIdx.x] = s;
    __syncthreads();
    for (int off = 128; off > 0; off >>= 1) {
        if (threadIdx.x < (unsigned)off) red[threadIdx.x] += red[threadIdx.x + off];
        __syncthreads();
    }
    if (threadIdx.x == 0) g_inv[b] = 1.0f / red[0];
}

// f32 -> fp16 hi/lo split (flat) — W only
__global__ void split_flat(const float4* __restrict__ in,
                           uint2* __restrict__ hi, uint2* __restrict__ lo, int n4) {
    int i = blockIdx.x * blockDim.x + threadIdx.x;
    if (i >= n4) return;
    float4 v = in[i];
    __half h0 = __float2half_rn(v.x), h1 = __float2half_rn(v.y);
    __half h2 = __float2half_rn(v.z), h3 = __float2half_rn(v.w);
    uint2 hp, lp;
    hp.x = (uint32_t)__half_as_ushort(h0) | ((uint32_t)__half_as_ushort(h1) << 16);
    hp.y = (uint32_t)__half_as_ushort(h2) | ((uint32_t)__half_as_ushort(h3) << 16);
    lp.x = packhf(v.x - __half2float(h0), v.y - __half2float(h1));
    lp.y = packhf(v.z - __half2float(h2), v.w - __half2float(h3));
    hi[i] = hp;
    lo[i] = lp;
}

// per-batch transpose + fp16 cast (f32 input), PACKED uint32 stores
__global__ void transpose_cast(const float* __restrict__ in,
                               __half* __restrict__ hi, int rows, int cols) {
    __shared__ float t[32][33];
    const size_t off = (size_t)blockIdx.z * rows * cols;
    const int c0 = blockIdx.x * 32, r0 = blockIdx.y * 32;
    const int x = threadIdx.x & 31, y0 = threadIdx.x >> 5;
#pragma unroll
    for (int yy = y0; yy < 32; yy += 8)
        t[yy][x] = in[off + (size_t)(r0 + yy) * cols + c0 + x];
    __syncthreads();
    const int sx = threadIdx.x & 15, sy = threadIdx.x >> 4;
#pragma unroll
    for (int cc = sy; cc < 32; cc += 16) {
        uint32_t pk = packhf(t[2 * sx][cc], t[2 * sx + 1][cc]);
        *(uint32_t*)(hi + off + (size_t)(c0 + cc) * rows + r0 + 2 * sx) = pk;
    }
}

// same, fp16 input (for TT = transpose of fp16 T view)
__global__ void transpose_h(const __half* __restrict__ in,
                            __half* __restrict__ hi, int rows, int cols) {
    __shared__ float t[32][33];
    const size_t off = (size_t)blockIdx.z * rows * cols;
    const int c0 = blockIdx.x * 32, r0 = blockIdx.y * 32;
    const int x = threadIdx.x & 31, y0 = threadIdx.x >> 5;
#pragma unroll
    for (int yy = y0; yy < 32; yy += 8)
        t[yy][x] = __half2float(in[off + (size_t)(r0 + yy) * cols + c0 + x]);
    __syncthreads();
    const int sx = threadIdx.x & 15, sy = threadIdx.x >> 4;
#pragma unroll
    for (int cc = sy; cc < 32; cc += 16) {
        uint32_t pk = packhf(t[2 * sx][cc], t[2 * sx + 1][cc]);
        *(uint32_t*)(hi + off + (size_t)(c0 + cc) * rows + r0 + 2 * sx) = pk;
    }
}

// ---------------------------------------------------------------------------
// PTX helpers (sm_80 baseline — compiles on plain compute_103)
// ---------------------------------------------------------------------------
__device__ __forceinline__ uint32_t s2u(const void* p) {
    uint32_t a;
    asm("{ .reg .u64 t; cvta.to.shared.u64 t, %1; cvt.u32.u64 %0, t; }" : "=r"(a) : "l"(p));
    return a;
}
__device__ __forceinline__ void cp16(uint32_t d, const void* g) {
    asm volatile("cp.async.cg.shared.global [%0], [%1], 16;" :: "r"(d), "l"(g));
}
#define LDM4(r, addr) \
    asm volatile("ldmatrix.sync.aligned.m8n8.x4.shared.b16 {%0,%1,%2,%3}, [%4];" \
        : "=r"((r)[0]), "=r"((r)[1]), "=r"((r)[2]), "=r"((r)[3]) : "r"(addr))
#define MMAH(c, a0, a1, a2, a3, b0, b1) \
    asm volatile("mma.sync.aligned.m16n8k16.row.col.f32.f16.f16.f32 " \
        "{%0,%1,%2,%3}, {%4,%5,%6,%7}, {%8,%9}, {%0,%1,%2,%3};" \
        : "+f"((c)[0]), "+f"((c)[1]), "+f"((c)[2]), "+f"((c)[3]) \
        : "r"(a0), "r"(a1), "r"(a2), "r"(a3), "r"(b0), "r"(b1))

// ---------------------------------------------------------------------------
// fp16 mma.sync GEMM, CTA 128x128, warp tile 64x32, KC=32, NSTG-stage cp.async
//   D[m,n] = sum_k A[m,k]*B[n,k]   (K-major fp16)
// TERMS=2: ahi*bhi + alo*bhi  (= A*Bhi, A exact)       [G2: 3-stage]
// TERMS=1: ahi*bhi                                      [G1/G3: 4-stage]
// EPI 0: Shat = relu(acc/256)^2 -> g_Shat (fp16)
// EPI 1: T = acc + bias[row]     -> g_Tf16 (fp16, ld 2304)
// EPI 2: Y = acc * inv^2*65536   -> outY (f32, ld 256)
// ---------------------------------------------------------------------------
template <int EPI, int TERMS, int NSTG>
__global__ void __launch_bounds__(256, 2)
mm_fp16(const __half* __restrict__ Ah, const __half* __restrict__ Al,
        const __half* __restrict__ Bh,
        int lda, int ldb, size_t bA, size_t bB, int K,
        const float* __restrict__ bias, float* __restrict__ outY)
{
    constexpr uint32_t STG = (TERMS == 2) ? STG2 : STG1;
    constexpr uint32_t oBh = (TERMS == 2) ? 20480u : 10240u;

    extern __shared__ char smv[];
    const uint32_t sb = s2u(smv);
    const int tid = threadIdx.x;
    const int bz = blockIdx.z;
    const int m0 = blockIdx.y * 128, n0 = blockIdx.x * 128;
    const int w = tid >> 5, l = tid & 31;
    const int wm = w >> 2, wn = w & 3;       // 2 x 4 warps, warp tile 64x32

    const int r = tid >> 1, c = tid & 1;
    const __half* pAh = Ah + (size_t)bz * bA + (size_t)(m0 + r) * lda + c * 16;
    const __half* pAl = (TERMS == 2) ? (Al + (size_t)(m0 + r) * lda + c * 16) : nullptr;
    const __half* pBh = Bh + (size_t)bz * bB + (size_t)(n0 + r) * ldb + c * 16;
    const uint32_t dA = sb + r * 80 + c * 32;
    const uint32_t dB = sb + oBh + r * 80 + c * 32;

    const int sub = l >> 3;
    const uint32_t aOff = (uint32_t)((wm * 64 + (sub & 1) * 8 + (l & 7)) * 80 + (sub >> 1) * 16);
    const uint32_t bOff = (uint32_t)(oBh + (wn * 32 + (l >> 4) * 8 + (l & 7)) * 80 + ((l >> 3) & 1) * 16);

    float acc[4][4][4];
#pragma unroll
    for (int i = 0; i < 4; i++)
#pragma unroll
        for (int j = 0; j < 4; j++)
#pragma unroll
            for (int q = 0; q < 4; q++) acc[i][j][q] = 0.f;

#define LOAD_STAGE(kc, slot) do { \
        const uint32_t so = (uint32_t)(slot) * STG; \
        const int ko = (kc) * 32; \
        cp16(dA + so,      pAh + ko); \
        cp16(dA + so + 16, pAh + ko + 8); \
        cp16(dB + so,      pBh + ko); \
        cp16(dB + so + 16, pBh + ko + 8); \
        if (TERMS == 2) { \
            cp16(dA + so + 10240, pAl + ko); \
            cp16(dA + so + 10256, pAl + ko + 8); \
        } \
        asm volatile("cp.async.commit_group;"); \
    } while (0)

    const int KN = K / 32;
#pragma unroll
    for (int p = 0; p < NSTG - 1; p++) LOAD_STAGE(p, p);

    int slot = 0;
    for (int kc = 0; kc < KN; kc++) {
        if (NSTG == 4) asm volatile("cp.async.wait_group 2;");
        else           asm volatile("cp.async.wait_group 1;");
        __syncthreads();
        if (kc + NSTG - 1 < KN) LOAD_STAGE(kc + NSTG - 1, (kc + NSTG - 1) % NSTG);
        const uint32_t s0 = sb + slot * STG;
        slot++; if (slot == NSTG) slot = 0;
#pragma unroll
        for (int ks = 0; ks < 2; ks++) {
            uint32_t bfh[4][2];
            const uint32_t b0a = s0 + bOff + ks * 32;
#pragma unroll
            for (int p = 0; p < 2; p++) {
                uint32_t t4[4];
                LDM4(t4, b0a + p * (16 * 80));
                bfh[2 * p][0] = t4[0]; bfh[2 * p][1] = t4[1];
                bfh[2 * p + 1][0] = t4[2]; bfh[2 * p + 1][1] = t4[3];
            }
            const uint32_t a0a = s0 + aOff + ks * 32;
#pragma unroll
            for (int i = 0; i < 4; i++) {
                uint32_t ah[4];
                LDM4(ah, a0a + i * 1280);
#pragma unroll
                for (int j = 0; j < 4; j++)
                    MMAH(acc[i][j], ah[0], ah[1], ah[2], ah[3], bfh[j][0], bfh[j][1]);
                if (TERMS == 2) {
                    uint32_t al4[4];
                    LDM4(al4, a0a + i * 1280 + 10240);
#pragma unroll
                    for (int j = 0; j < 4; j++)
                        MMAH(acc[i][j], al4[0], al4[1], al4[2], al4[3], bfh[j][0], bfh[j][1]);
                }
            }
        }
    }

    // epilogue
    float factor = 0.f;
    if (EPI == 2) {
        float inv = g_inv[bz];
        factor = inv * inv * 65536.f;
    }
    const int quad = l >> 2, tq = l & 3;
#pragma unroll
    for (int i = 0; i < 4; i++) {
#pragma unroll
        for (int half = 0; half < 2; half++) {
            const int rr = m0 + wm * 64 + i * 16 + quad + half * 8;
            float bvv = 0.f;
            if (EPI == 1) bvv = bias[rr];
#pragma unroll
            for (int j = 0; j < 4; j++) {
                const int col = n0 + wn * 32 + j * 8 + tq * 2;
                float v0 = acc[i][j][half * 2 + 0];
                float v1 = acc[i][j][half * 2 + 1];
                if (EPI == 0) {
                    v0 = fmaxf(v0 * 0.00390625f, 0.f); v0 *= v0;
                    v1 = fmaxf(v1 * 0.00390625f, 0.f); v1 *= v1;
                    size_t base = (size_t)bz * HWDIM * HWDIM + (size_t)rr * HWDIM + col;
                    *(uint32_t*)(g_Shat + base) = packhf(v0, v1);
                } else if (EPI == 1) {
                    size_t base = (size_t)bz * PB + (size_t)rr * HWDIM + col;
                    *(uint32_t*)(g_Tf16 + base) = packhf(v0 + bvv, v1 + bvv);
                } else {
                    float2 vv; vv.x = v0 * factor; vv.y = v1 * factor;
                    *(float2*)(outY + (size_t)bz * PB + (size_t)rr * CDIM + col) = vv;
                }
            }
        }
    }
#undef LOAD_STAGE
}

// ---------------------------------------------------------------------------
// Host launch — two-stream fork/join (graph-capture-safe pattern):
//   s0: cast_sumsq ─────────────► G1 ─────────► G3
//         │(evRoot)     (evXT)▲        (evAux)▲
//   s1: ──┴─ split, XT ─┴─ finalize, G2, TT ──┘
// ---------------------------------------------------------------------------
extern "C" void kernel_launch(void* const* d_in, const int* in_sizes, int n_in,
                              void* d_out, int out_size)
{
    const float* x    = (const float*)d_in[0];
    const float* W    = (const float*)d_in[1];
    const float* bias = (const float*)d_in[2];
    float* out        = (float*)d_out;

    void *pXhi, *pXThi, *pWhi, *pWlo, *pShat, *pTThi, *pTf;
    cudaGetSymbolAddress(&pXhi,  g_Xhi);
    cudaGetSymbolAddress(&pXThi, g_XThi);
    cudaGetSymbolAddress(&pWhi,  g_Whi);
    cudaGetSymbolAddress(&pWlo,  g_Wlo);
    cudaGetSymbolAddress(&pShat, g_Shat);
    cudaGetSymbolAddress(&pTThi, g_TThi);
    cudaGetSymbolAddress(&pTf,   g_Tf16);

    static bool init_done = false;
    static cudaStream_t s1;
    static cudaEvent_t evRoot, evXT, evAux;
    if (!init_done) {
        cudaFuncSetAttribute(mm_fp16<0, 1, 4>, cudaFuncAttributeMaxDynamicSharedMemorySize, SMEM_G1);
        cudaFuncSetAttribute(mm_fp16<1, 2, 3>, cudaFuncAttributeMaxDynamicSharedMemorySize, SMEM_G2);
        cudaFuncSetAttribute(mm_fp16<2, 1, 4>, cudaFuncAttributeMaxDynamicSharedMemorySize, SMEM_G1);
        cudaStreamCreateWithFlags(&s1, cudaStreamNonBlocking);
        cudaEventCreateWithFlags(&evRoot, cudaEventDisableTiming);
        cudaEventCreateWithFlags(&evXT,   cudaEventDisableTiming);
        cudaEventCreateWithFlags(&evAux,  cudaEventDisableTiming);
        init_done = true;
    }

    cudaStream_t s0 = 0;   // default (capture) stream

    // fork s1 from s0
    cudaEventRecord(evRoot, s0);
    cudaStreamWaitEvent(s1, evRoot, 0);

    // s0: fused x cast + sumsq partials (producer for G1-A and finalize)
    cast_sumsq<<<NPART, 256, 0, s0>>>((const float4*)x, (uint2*)pXhi);

    // s1: W split + XT transpose (independent of cast)
    split_flat<<<(CDIM * CDIM / 4 + 255) / 256, 256, 0, s1>>>(
        (const float4*)W, (uint2*)pWhi, (uint2*)pWlo, CDIM * CDIM / 4);
    {
        dim3 g(HWDIM / 32, CDIM / 32, BATCH);
        transpose_cast<<<g, 256, 0, s1>>>(x, (__half*)pXThi, CDIM, HWDIM);
    }
    cudaEventRecord(evXT, s1);         // XT ready (for G1 on s0)

    // s1 also needs cast's partials for finalize: wait on s0's cast
    cudaEventRecord(evRoot, s0);       // re-record after cast
    cudaStreamWaitEvent(s1, evRoot, 0);

    // s1: finalize inv, GEMM2, TT  (all off the G1 critical path)
    finalize_inv<<<BATCH, 256, 0, s1>>>();
    mm_fp16<1, 2, 3><<<dim3(HWDIM / 128, CDIM / 128, BATCH), 256, SMEM_G2, s1>>>(
        (const __half*)pWhi, (const __half*)pWlo, (const __half*)pXThi,
        CDIM, CDIM, 0, (size_t)PB, CDIM, bias, nullptr);
    {
        dim3 g(CDIM / 32, HWDIM / 32, BATCH);
        transpose_h<<<g, 256, 0, s1>>>((const __half*)pTf, (__half*)pTThi, HWDIM, CDIM);
    }
    cudaEventRecord(evAux, s1);

    // s0: G1 (needs Xhi from cast [same stream] + XThi via evXT)
    cudaStreamWaitEvent(s0, evXT, 0);
    mm_fp16<0, 1, 4><<<dim3(HWDIM / 128, HWDIM / 128, BATCH), 256, SMEM_G1, s0>>>(
        (const __half*)pXhi, nullptr, (const __half*)pXThi,
        CDIM, CDIM, (size_t)PB, (size_t)PB, CDIM, nullptr, nullptr);

    // join: G3 needs Shat (s0), TThi + inv (s1 via evAux)
    cudaStreamWaitEvent(s0, evAux, 0);
    mm_fp16<2, 1, 4><<<dim3(CDIM / 128, HWDIM / 128, BATCH), 256, SMEM_G1, s0>>>(
        (const __half*)pShat, nullptr, (const __half*)pTThi,
        HWDIM, HWDIM, (size_t)HWDIM * HWDIM, (size_t)PB, HWDIM, nullptr, out);
}